// round 6
// baseline (speedup 1.0000x reference)
#include <cuda_runtime.h>
#include <cstdint>
#include <math.h>

#define B_ 2
#define H_ 16
#define S_ 2048
#define E_ 64
#define NTOK (B_*S_*H_)            // 65536
#define SSTR 68                    // Ss row stride (floats)

// Scratch for projected Q,K,V in [B,H,S,E] layout (48 MB, static device mem)
__device__ float g_q[B_*H_*S_*E_];
__device__ float g_k[B_*H_*S_*E_];
__device__ float g_v[B_*H_*S_*E_];

// ---------------------------------------------------------------------------
// Packed 2xfp32 FMA helpers (sm_100+ PTX: fma.rn.f32x2)
// ---------------------------------------------------------------------------
__device__ __forceinline__ void ffma2(unsigned long long& d,
                                      unsigned long long a,
                                      unsigned long long b) {
    asm("fma.rn.f32x2 %0, %1, %2, %0;" : "+l"(d) : "l"(a), "l"(b));
}
__device__ __forceinline__ void fmul2(unsigned long long& d,
                                      unsigned long long s) {
    asm("mul.rn.f32x2 %0, %0, %1;" : "+l"(d) : "l"(s));
}
__device__ __forceinline__ unsigned long long pack2(float x, float y) {
    unsigned long long r;
    asm("mov.b64 %0, {%1, %2};" : "=l"(r) : "f"(x), "f"(y));
    return r;
}
__device__ __forceinline__ float2 unpack2(unsigned long long v) {
    float lo, hi;
    asm("mov.b64 {%0, %1}, %2;" : "=f"(lo), "=f"(hi) : "l"(v));
    return make_float2(lo, hi);
}

// ---------------------------------------------------------------------------
// Exact JAX threefry2x32, key=(0,42), partitionable counter mode:
// element i -> counter (0,i), output fold x0 ^ x1.
// ---------------------------------------------------------------------------
__device__ __forceinline__ uint32_t threefry_bits_42(uint32_t c1) {
    const uint32_t ks0 = 0u;
    const uint32_t ks1 = 42u;
    const uint32_t ks2 = 0x1BD11BDAu ^ 0u ^ 42u;
    uint32_t x0 = 0u + ks0;
    uint32_t x1 = c1 + ks1;
#define TF_R(r) { x0 += x1; x1 = __funnelshift_l(x1, x1, (r)); x1 ^= x0; }
    TF_R(13) TF_R(15) TF_R(26) TF_R(6)
    x0 += ks1; x1 += ks2 + 1u;
    TF_R(17) TF_R(29) TF_R(16) TF_R(24)
    x0 += ks2; x1 += ks0 + 2u;
    TF_R(13) TF_R(15) TF_R(26) TF_R(6)
    x0 += ks0; x1 += ks1 + 3u;
    TF_R(17) TF_R(29) TF_R(16) TF_R(24)
    x0 += ks1; x1 += ks2 + 4u;
    TF_R(13) TF_R(15) TF_R(26) TF_R(6)
    x0 += ks2; x1 += ks0 + 5u;
#undef TF_R
    return x0 ^ x1;
}

__device__ __forceinline__ float jax_uniform(uint32_t bits) {
    return __uint_as_float((bits >> 9) | 0x3f800000u) - 1.0f;
}

// ---------------------------------------------------------------------------
// Projection: out[b,h,s,e] = sum_d x[b,s,h,d] * W[e,d] + bias[e]
// ---------------------------------------------------------------------------
__global__ __launch_bounds__(256) void proj_kernel(
    const float* __restrict__ x, const float* __restrict__ W,
    const float* __restrict__ bias, int which)
{
    __shared__ float Xs[64][65];
    __shared__ float Ws[64][65];
    __shared__ float bs[64];

    float* out = (which == 0) ? g_q : (which == 1) ? g_k : g_v;

    const int tid = threadIdx.x;
    const int n0  = blockIdx.x * 64;

    #pragma unroll
    for (int it = 0; it < 4; ++it) {
        int elem = tid * 4 + it * 1024;
        int r = elem >> 6, c = elem & 63;
        float4 w4 = *(const float4*)(W + elem);
        Ws[r][c] = w4.x; Ws[r][c+1] = w4.y; Ws[r][c+2] = w4.z; Ws[r][c+3] = w4.w;
        float4 x4 = *(const float4*)(x + (size_t)n0 * 64 + elem);
        Xs[r][c] = x4.x; Xs[r][c+1] = x4.y; Xs[r][c+2] = x4.z; Xs[r][c+3] = x4.w;
    }
    if (tid < 64) bs[tid] = bias[tid];
    __syncthreads();

    const int tx = tid & 15, ty = tid >> 4;
    float acc[4][4] = {};
    #pragma unroll 8
    for (int d = 0; d < 64; ++d) {
        float a[4], b[4];
        #pragma unroll
        for (int i = 0; i < 4; ++i) a[i] = Xs[ty*4+i][d];
        #pragma unroll
        for (int j = 0; j < 4; ++j) b[j] = Ws[tx*4+j][d];
        #pragma unroll
        for (int i = 0; i < 4; ++i)
            #pragma unroll
            for (int j = 0; j < 4; ++j)
                acc[i][j] = fmaf(a[i], b[j], acc[i][j]);
    }

    #pragma unroll
    for (int i = 0; i < 4; ++i) {
        int n   = n0 + ty*4 + i;
        int b_  = n >> 15;
        int rem = n & 32767;
        int s   = rem >> 4;
        int h   = n & 15;
        float* op = out + ((((size_t)b_ * H_ + h) * S_ + s) << 6);
        #pragma unroll
        for (int j = 0; j < 4; ++j) {
            int e = tx*4 + j;
            op[e] = acc[i][j] + bs[e];
        }
    }
}

// ---------------------------------------------------------------------------
// Flash attention: XOR-swizzled smem, f32x2 packed-FMA GEMM phases,
// V stored transposed, ballot-gated exact threefry dropout.
// Smem: Qs[64*64], Ks[64*64], Vt[64*64], Ss[64*SSTR], m/Z/f[64 each]
// ---------------------------------------------------------------------------
#define SMEM_FLOATS (3*64*64 + 64*SSTR + 192)   // 16832 floats = 67328 B

__global__ __launch_bounds__(256, 2) void attn_kernel(
    const float* __restrict__ mask,
    const float* __restrict__ inv_scale,
    float* __restrict__ out)
{
    extern __shared__ float sm[];
    float* Qs = sm;                  // swizzled, stride 64
    float* Ks = sm + 64*64;          // swizzled, stride 64
    float* Vt = sm + 2*64*64;        // transposed + swizzled, stride 64
    float* Ss = sm + 3*64*64;        // stride SSTR
    float* m_s = Ss + 64*SSTR;
    float* Z_s = m_s + 64;
    float* f_s = Z_s + 64;

    const int tid  = threadIdx.x;
    const int s0   = blockIdx.x * 64;
    const int h    = blockIdx.y;
    const int b    = blockIdx.z;
    const float rscale = 1.0f / inv_scale[0];

    const float* Qg = g_q + ((((size_t)b * H_ + h) * S_ + s0) << 6);
    const float* Kg = g_k + ((((size_t)b * H_ + h) * S_) << 6);
    const float* Vg = g_v + ((((size_t)b * H_ + h) * S_) << 6);
    const float* Mg = mask + ((size_t)b * S_ + s0) * S_;

    // load Q tile -> swizzled rows: chunk c4 of row r at c4 ^ (r & 15)
    #pragma unroll
    for (int it = 0; it < 4; ++it) {
        int elem = tid * 4 + it * 1024;
        int r = elem >> 6, c4 = (elem >> 2) & 15;
        *(float4*)&Qs[r*64 + ((c4 ^ (r & 15)) << 2)] = *(const float4*)(Qg + elem);
    }
    if (tid < 64) { m_s[tid] = -INFINITY; Z_s[tid] = 0.0f; }

    const int tx = tid & 15, ty = tid >> 4;
    const int lane = tid & 31, warp = tid >> 5;

    unsigned long long acc2[4][4];   // packed pair-sums over t; cols 4tx+j
    #pragma unroll
    for (int i = 0; i < 4; ++i)
        #pragma unroll
        for (int j = 0; j < 4; ++j) acc2[i][j] = 0ull;

    for (int t0 = 0; t0 < S_; t0 += 64) {
        __syncthreads();
        // K tile (swizzled) + mask tile into Ss
        #pragma unroll
        for (int it = 0; it < 4; ++it) {
            int elem = tid * 4 + it * 1024;
            int r = elem >> 6, c = elem & 63, c4 = c >> 2;
            *(float4*)&Ks[r*64 + ((c4 ^ (r & 15)) << 2)] =
                *(const float4*)(Kg + (((size_t)t0) << 6) + elem);
            *(float4*)&Ss[r*SSTR + c] = *(const float4*)(Mg + (size_t)r * S_ + t0 + c);
        }
        // V tile: transposed-register load -> Vt[col][t], double-XOR swizzle
        #pragma unroll
        for (int it = 0; it < 4; ++it) {
            int unit = tid + it * 256;          // 0..1023
            int col = unit & 63, tc = unit >> 6;
            const float* vp = Vg + (((size_t)(t0 + tc*4)) << 6) + col;
            float4 v4;
            v4.x = vp[0]; v4.y = vp[64]; v4.z = vp[128]; v4.w = vp[192];
            int swz = tc ^ ((col >> 2) & 15) ^ ((col & 3) << 2);
            *(float4*)&Vt[col*64 + (swz << 2)] = v4;
        }
        __syncthreads();

        // S[4ty+i][tx+16j] = (Q K^T)*rscale + mask, packed over e
        {
            unsigned long long sacc2[4][4];
            #pragma unroll
            for (int i = 0; i < 4; ++i)
                #pragma unroll
                for (int j = 0; j < 4; ++j) sacc2[i][j] = 0ull;

            #pragma unroll
            for (int e4 = 0; e4 < 16; ++e4) {
                ulonglong2 qv[4], kv[4];
                #pragma unroll
                for (int i = 0; i < 4; ++i) {
                    int ri = 4*ty + i;
                    qv[i] = *(const ulonglong2*)&Qs[ri*64 + ((e4 ^ (ri & 15)) << 2)];
                }
                #pragma unroll
                for (int j = 0; j < 4; ++j) {
                    int rj = tx + 16*j;        // rj & 15 == tx
                    kv[j] = *(const ulonglong2*)&Ks[rj*64 + ((e4 ^ tx) << 2)];
                }
                #pragma unroll
                for (int i = 0; i < 4; ++i)
                    #pragma unroll
                    for (int j = 0; j < 4; ++j) {
                        ffma2(sacc2[i][j], qv[i].x, kv[j].x);
                        ffma2(sacc2[i][j], qv[i].y, kv[j].y);
                    }
            }
            #pragma unroll
            for (int i = 0; i < 4; ++i)
                #pragma unroll
                for (int j = 0; j < 4; ++j) {
                    float2 p = unpack2(sacc2[i][j]);
                    int idx = (4*ty+i)*SSTR + tx + 16*j;
                    Ss[idx] = fmaf(p.x + p.y, rscale, Ss[idx]);
                }
        }
        __syncthreads();

        // online softmax + ballot-gated exact threefry dropout
        #pragma unroll 1
        for (int k = 0; k < 8; ++k) {
            int r = warp * 8 + k;
            float v0 = Ss[r*SSTR + lane];
            float v1 = Ss[r*SSTR + lane + 32];
            float mx = fmaxf(v0, v1);
            #pragma unroll
            for (int off = 16; off; off >>= 1)
                mx = fmaxf(mx, __shfl_xor_sync(0xffffffffu, mx, off));
            float m_old = m_s[r];
            float m_new = fmaxf(m_old, mx);
            float p0 = __expf(v0 - m_new);
            float p1 = __expf(v1 - m_new);
            float zt = p0 + p1;
            #pragma unroll
            for (int off = 16; off; off >>= 1)
                zt += __shfl_xor_sync(0xffffffffu, zt, off);
            if (lane == 0) {
                float f = __expf(m_old - m_new);
                f_s[r] = f;
                Z_s[r] = Z_s[r] * f + zt;
                m_s[r] = m_new;
            }
            unsigned bal = __ballot_sync(0xffffffffu,
                                         (p0 >= 1e-10f) | (p1 >= 1e-10f));
            if (bal) {
                uint32_t base = (((uint32_t)(b * H_ + h) * (uint32_t)S_
                                  + (uint32_t)(s0 + r)) * (uint32_t)S_)
                              + (uint32_t)t0;
                uint32_t bits0 = threefry_bits_42(base + (uint32_t)lane);
                uint32_t bits1 = threefry_bits_42(base + (uint32_t)lane + 32u);
                Ss[r*SSTR + lane]      = (jax_uniform(bits0) < 0.9f) ? p0 : 0.0f;
                Ss[r*SSTR + lane + 32] = (jax_uniform(bits1) < 0.9f) ? p1 : 0.0f;
            } else {
                Ss[r*SSTR + lane]      = p0;
                Ss[r*SSTR + lane + 32] = p1;
            }
        }
        __syncthreads();

        // PV accumulate, packed over t pairs via V^T
        {
            #pragma unroll
            for (int i = 0; i < 4; ++i) {
                float f = f_s[4*ty+i];
                unsigned long long ff = pack2(f, f);
                #pragma unroll
                for (int j = 0; j < 4; ++j) fmul2(acc2[i][j], ff);
            }
            #pragma unroll
            for (int tc = 0; tc < 16; ++tc) {
                int t = tc << 2;
                ulonglong2 sv[4], vv[4];
                #pragma unroll
                for (int i = 0; i < 4; ++i)
                    sv[i] = *(const ulonglong2*)&Ss[(4*ty+i)*SSTR + t];
                #pragma unroll
                for (int j = 0; j < 4; ++j) {
                    int col = 4*tx + j;
                    int swz = tc ^ tx ^ (j << 2);
                    vv[j] = *(const ulonglong2*)&Vt[col*64 + (swz << 2)];
                }
                #pragma unroll
                for (int i = 0; i < 4; ++i)
                    #pragma unroll
                    for (int j = 0; j < 4; ++j) {
                        ffma2(acc2[i][j], sv[i].x, vv[j].x);
                        ffma2(acc2[i][j], sv[i].y, vv[j].y);
                    }
            }
        }
    }

    // write: out[b,h,s,4tx..4tx+3] = (lo+hi) / (Z * 0.9)
    #pragma unroll
    for (int i = 0; i < 4; ++i) {
        int r = 4*ty + i;
        float invz = 1.0f / (Z_s[r] * 0.9f);
        float* op = out + ((((size_t)b * H_ + h) * S_ + (s0 + r)) << 6);
        float4 o4;
        float2 a0 = unpack2(acc2[i][0]);
        float2 a1 = unpack2(acc2[i][1]);
        float2 a2 = unpack2(acc2[i][2]);
        float2 a3 = unpack2(acc2[i][3]);
        o4.x = (a0.x + a0.y) * invz;
        o4.y = (a1.x + a1.y) * invz;
        o4.z = (a2.x + a2.y) * invz;
        o4.w = (a3.x + a3.y) * invz;
        *(float4*)(op + 4*tx) = o4;
    }
}

// ---------------------------------------------------------------------------
extern "C" void kernel_launch(void* const* d_in, const int* in_sizes, int n_in,
                              void* d_out, int out_size)
{
    const float* query     = (const float*)d_in[0];
    const float* key       = (const float*)d_in[1];
    const float* value     = (const float*)d_in[2];
    const float* attn_mask = (const float*)d_in[3];
    const float* inv_scale = (const float*)d_in[4];
    const float* Wq = (const float*)d_in[5];
    const float* bq = (const float*)d_in[6];
    const float* Wk = (const float*)d_in[7];
    const float* bk = (const float*)d_in[8];
    const float* Wv = (const float*)d_in[9];
    const float* bv = (const float*)d_in[10];
    float* out = (float*)d_out;

    const int nblk = NTOK / 64;   // 1024
    proj_kernel<<<nblk, 256>>>(query, Wq, bq, 0);
    proj_kernel<<<nblk, 256>>>(key,   Wk, bk, 1);
    proj_kernel<<<nblk, 256>>>(value, Wv, bv, 2);

    cudaFuncSetAttribute(attn_kernel,
                         cudaFuncAttributeMaxDynamicSharedMemorySize,
                         SMEM_FLOATS * (int)sizeof(float));
    dim3 grid(S_ / 64, H_, B_);
    attn_kernel<<<grid, 256, SMEM_FLOATS * sizeof(float)>>>(attn_mask, inv_scale, out);
}